// round 2
// baseline (speedup 1.0000x reference)
#include <cuda_runtime.h>
#include <math.h>

#define IDIM 128
#define HDIM 1024
#define CDIM 256
#define NITER 4
#define NTOK 2048          // B*T = 4*512
#define TOK_PER_BLK 8
#define NBLK (NTOK / TOK_PER_BLK)   // 256
#define NTHREADS 256
#define XPAD 384           // padded x_res length (382 used, 127 zero pad each side)
#define WPAD 129           // padded row stride for staged weight tiles
#define TS 12              // token stride (floats) in transposed activation arrays

__device__ float g_psum[NBLK];
__device__ float g_pcnt[NBLK];

struct __align__(16) Smem {
    float wstage[IDIM * WPAD];        // 128 x 129 staged (transposed) weight tile, 66048 B
    float xp[TOK_PER_BLK][XPAD];      // padded x_res per token
    float hT[CDIM][TS];               // h transposed: [channel][token], padded stride
    float xaT[IDIM][TS];              // x_attn transposed: [d][token]
    float yres[TOK_PER_BLK][IDIM];    // y residual
    float red[8];
    float red2[8];
    unsigned char ymask[TOK_PER_BLK][IDIM];
};

extern __shared__ unsigned char smem_raw[];

__global__ void __launch_bounds__(NTHREADS, 2)
net_main_kernel(const float* __restrict__ x, const float* __restrict__ y,
                const float* __restrict__ w1, const float* __restrict__ b1,
                const float* __restrict__ w2, const float* __restrict__ b2)
{
    Smem& sm = *reinterpret_cast<Smem*>(smem_raw);
    const int tid  = threadIdx.x;
    const int lane = tid & 31;
    const int wid  = tid >> 5;
    const int blk  = blockIdx.x;
    const int tok0 = blk * TOK_PER_BLK;

    // ---- zero padded x buffer ----
    for (int e = tid; e < TOK_PER_BLK * XPAD; e += NTHREADS)
        (&sm.xp[0][0])[e] = 0.f;
    __syncthreads();

    // ---- load x, y, mask; count unmasked ----
    float cnt = 0.f;
    for (int e = tid; e < TOK_PER_BLK * IDIM; e += NTHREADS) {
        int m = e >> 7, d = e & 127;
        sm.xp[m][127 + d] = x[(tok0 + m) * IDIM + d];
        float yv = y[(tok0 + m) * IDIM + d];
        sm.yres[m][d] = yv;
        unsigned char msk = (yv == 10000.0f) ? 1 : 0;
        sm.ymask[m][d] = msk;
        cnt += msk ? 0.f : 1.f;
    }

    float sqacc = 0.f;
    const int o   = tid & 127;     // output channel (phase C) / channel-in-chunk (phase B)
    const int g   = tid >> 7;      // token group: tokens 4g..4g+3

    for (int it = 0; it < NITER; ++it) {
        __syncthreads();   // yres/xp stable for phase A

        // ================= Phase A: per-warp token pipeline =================
        {
            const int m = wid;
            const float* xpm = sm.xp[m];
            const float* ym  = sm.yres[m];

            // ||y_res||^2
            float ny2 = 0.f;
            #pragma unroll
            for (int j = 0; j < 4; ++j) { float v = ym[lane + 32 * j]; ny2 += v * v; }
            #pragma unroll
            for (int off = 16; off; off >>= 1) ny2 += __shfl_xor_sync(~0u, ny2, off);
            float ny = sqrtf(ny2);

            // correlation + window norms, lane-interleaved shifts s = lane + 32k
            float num[8], dn[8];
            #pragma unroll
            for (int k = 0; k < 8; ++k) { num[k] = 0.f; dn[k] = 0.f; }
            #pragma unroll 4
            for (int d = 0; d < 128; ++d) {
                float yv = ym[d];
                const float* xb = xpm + d + lane;
                #pragma unroll
                for (int k = 0; k < 8; ++k) {
                    float xv = xb[32 * k];
                    num[k] = fmaf(yv, xv, num[k]);
                    dn[k]  = fmaf(xv, xv, dn[k]);
                }
            }
            // per-lane first-max, then warp first-max (ties -> smaller s)
            float best = -INFINITY; int bs = 0x7fffffff;
            #pragma unroll
            for (int k = 0; k < 8; ++k) {
                int s = lane + 32 * k;
                if (s < 255) {
                    float den = ny * sqrtf(dn[k]);
                    float sim = (den == 0.f) ? 0.f : num[k] / den;
                    if (sim > best) { best = sim; bs = s; }
                }
            }
            #pragma unroll
            for (int off = 16; off; off >>= 1) {
                float ob = __shfl_xor_sync(~0u, best, off);
                int   os = __shfl_xor_sync(~0u, bs,   off);
                if (ob > best || (ob == best && os < bs)) { best = ob; bs = os; }
            }
            const int idx = bs;

            // softmax attention: z = x_aug * y_res
            float xa[4], z[4];
            float zmax = -INFINITY;
            #pragma unroll
            for (int j = 0; j < 4; ++j) {
                int d = lane + 32 * j;
                xa[j] = xpm[idx + d];
                z[j]  = xa[j] * ym[d];
                zmax  = fmaxf(zmax, z[j]);
            }
            #pragma unroll
            for (int off = 16; off; off >>= 1) zmax = fmaxf(zmax, __shfl_xor_sync(~0u, zmax, off));
            float es = 0.f, e[4];
            #pragma unroll
            for (int j = 0; j < 4; ++j) { e[j] = expf(z[j] - zmax); es += e[j]; }
            #pragma unroll
            for (int off = 16; off; off >>= 1) es += __shfl_xor_sync(~0u, es, off);
            #pragma unroll
            for (int j = 0; j < 4; ++j) {
                int d = lane + 32 * j;
                sm.xaT[d][m] = xa[j] * (e[j] / es);   // x_attn
            }
            __syncwarp();
            // reverse shift: x_ele[d] = x_attn[d + 127 - idx]; x_res -= x_ele
            #pragma unroll
            for (int j = 0; j < 4; ++j) {
                int d = lane + 32 * j;
                int src = d + 127 - idx;
                float xe = (src >= 0 && src < 128) ? sm.xaT[src][m] : 0.f;
                sm.xp[m][127 + d] -= xe;
            }
        }
        __syncthreads();   // xaT ready for phase B; xp done

        // ================= Phase B: h = x_attn @ W1_slice^T + b1 =================
        for (int chunk = 0; chunk < 2; ++chunk) {
            // stage W1 rows [it*256 + chunk*128 .. +128) transposed into wstage[d][c]
            const float4* wg = reinterpret_cast<const float4*>(w1 + (size_t)(it * 256 + chunk * 128) * IDIM);
            #pragma unroll
            for (int r = 0; r < 16; ++r) {
                int f = tid + r * 256;           // 0..4095 float4s
                float4 v = wg[f];
                int c  = f >> 5;                 // channel 0..127
                int d0 = (f & 31) << 2;          // d base
                sm.wstage[(d0    ) * WPAD + c] = v.x;
                sm.wstage[(d0 + 1) * WPAD + c] = v.y;
                sm.wstage[(d0 + 2) * WPAD + c] = v.z;
                sm.wstage[(d0 + 3) * WPAD + c] = v.w;
            }
            __syncthreads();

            float bv = b1[it * 256 + chunk * 128 + o];
            float a0 = bv, a1 = bv, a2 = bv, a3 = bv;
            #pragma unroll 4
            for (int d = 0; d < 128; ++d) {
                float wv = sm.wstage[d * WPAD + o];
                float4 xv = *reinterpret_cast<const float4*>(&sm.xaT[d][4 * g]);
                a0 = fmaf(wv, xv.x, a0); a1 = fmaf(wv, xv.y, a1);
                a2 = fmaf(wv, xv.z, a2); a3 = fmaf(wv, xv.w, a3);
            }
            *reinterpret_cast<float4*>(&sm.hT[chunk * 128 + o][4 * g]) = make_float4(a0, a1, a2, a3);
            __syncthreads();   // protect wstage restage / hT consumers
        }

        // ================= Phase C: y_ele = h @ W2_slice^T + b2 =================
        float b2v = b2[o];
        float c0v = b2v, c1v = b2v, c2v = b2v, c3v = b2v;
        for (int chunk = 0; chunk < 2; ++chunk) {
            const float4* wg2 = reinterpret_cast<const float4*>(w2);
            #pragma unroll
            for (int r = 0; r < 16; ++r) {
                int f  = tid + r * 256;          // 0..4095
                int oo = f >> 5;                 // output row 0..127
                int c4 = (f & 31);               // float4 within 128-c chunk
                float4 v = wg2[(size_t)oo * (HDIM / 4) + (it * 64 + chunk * 32) + c4];
                int cb = c4 << 2;
                sm.wstage[(cb    ) * WPAD + oo] = v.x;
                sm.wstage[(cb + 1) * WPAD + oo] = v.y;
                sm.wstage[(cb + 2) * WPAD + oo] = v.z;
                sm.wstage[(cb + 3) * WPAD + oo] = v.w;
            }
            __syncthreads();
            #pragma unroll 4
            for (int c = 0; c < 128; ++c) {
                float wv = sm.wstage[c * WPAD + o];
                float4 hv = *reinterpret_cast<const float4*>(&sm.hT[chunk * 128 + c][4 * g]);
                c0v = fmaf(wv, hv.x, c0v); c1v = fmaf(wv, hv.y, c1v);
                c2v = fmaf(wv, hv.z, c2v); c3v = fmaf(wv, hv.w, c3v);
            }
            __syncthreads();
        }

        // ---- masked squared error + y_res update ----
        #pragma unroll
        for (int j = 0; j < 4; ++j) {
            int m = 4 * g + j;
            float ye = (j == 0) ? c0v : (j == 1) ? c1v : (j == 2) ? c2v : c3v;
            float yr = sm.yres[m][o];
            if (!sm.ymask[m][o]) { float dd = ye - yr; sqacc += dd * dd; }
            sm.yres[m][o] = yr - ye;
        }
        // next-iteration top __syncthreads orders these writes before phase A
    }

    // ---- block reduction of sq sum and unmasked count ----
    #pragma unroll
    for (int off = 16; off; off >>= 1) {
        sqacc += __shfl_xor_sync(~0u, sqacc, off);
        cnt   += __shfl_xor_sync(~0u, cnt,   off);
    }
    if (lane == 0) { sm.red[wid] = sqacc; sm.red2[wid] = cnt; }
    __syncthreads();
    if (tid == 0) {
        float s = 0.f, c = 0.f;
        #pragma unroll
        for (int w = 0; w < 8; ++w) { s += sm.red[w]; c += sm.red2[w]; }
        g_psum[blk] = s;
        g_pcnt[blk] = c;
    }
}

__global__ void net_final_kernel(float* __restrict__ out)
{
    __shared__ float ss[NBLK];
    __shared__ float sc[NBLK];
    int t = threadIdx.x;
    ss[t] = g_psum[t];
    sc[t] = g_pcnt[t];
    __syncthreads();
    for (int off = 128; off; off >>= 1) {
        if (t < off) { ss[t] += ss[t + off]; sc[t] += sc[t + off]; }
        __syncthreads();
    }
    if (t == 0) out[0] = ss[0] / (4.0f * sc[0]);
}

extern "C" void kernel_launch(void* const* d_in, const int* in_sizes, int n_in,
                              void* d_out, int out_size)
{
    (void)in_sizes; (void)n_in; (void)out_size;
    const float* x  = (const float*)d_in[0];
    const float* y  = (const float*)d_in[1];
    const float* w1 = (const float*)d_in[2];
    const float* b1 = (const float*)d_in[3];
    const float* w2 = (const float*)d_in[4];
    const float* b2 = (const float*)d_in[5];
    float* out = (float*)d_out;

    cudaFuncSetAttribute(net_main_kernel,
                         cudaFuncAttributeMaxDynamicSharedMemorySize,
                         (int)sizeof(Smem));
    net_main_kernel<<<NBLK, NTHREADS, sizeof(Smem)>>>(x, y, w1, b1, w2, b2);
    net_final_kernel<<<1, NBLK>>>(out);
}

// round 3
// speedup vs baseline: 2.1946x; 2.1946x over previous
#include <cuda_runtime.h>
#include <math.h>

#define IDIM 128
#define HDIM 1024
#define NITER 4
#define NTOK 2048
#define TOK_PER_BLK 8
#define NBLK (NTOK / TOK_PER_BLK)   // 256
#define NTHREADS 256
#define XPAD 384            // padded x_res (data at [127,254], zeros elsewhere)
#define WST_STRIDE 33       // float4 stride per staged weight row (conflict-free)
#define HROW 264            // h row stride in floats (16B-aligned rows)

__device__ float g_psum[NBLK];
__device__ float g_pcnt[NBLK];

struct __align__(16) Smem {
    float4 wst[IDIM * WST_STRIDE];     // 128 rows x 33 float4 = 67584 B
    float  xp[TOK_PER_BLK][XPAD];      // 12288 B
    float  xa[TOK_PER_BLK][IDIM];      // x_attn, token-major, 4096 B
    float  h[TOK_PER_BLK][HROW];       // hidden, token-major, 8448 B
    float  yres[TOK_PER_BLK][IDIM];    // 4096 B
    float  red[8];
    float  red2[8];
    unsigned char ymask[TOK_PER_BLK][IDIM];  // 1024 B
};

extern __shared__ unsigned char smem_raw[];

__global__ void __launch_bounds__(NTHREADS, 2)
net_main_kernel(const float* __restrict__ x, const float* __restrict__ y,
                const float* __restrict__ w1, const float* __restrict__ b1,
                const float* __restrict__ w2, const float* __restrict__ b2)
{
    Smem& sm = *reinterpret_cast<Smem*>(smem_raw);
    const int tid  = threadIdx.x;
    const int lane = tid & 31;
    const int wid  = tid >> 5;
    const int blk  = blockIdx.x;
    const int tok0 = blk * TOK_PER_BLK;

    // ---- zero padded x buffer ----
    for (int e = tid; e < TOK_PER_BLK * XPAD; e += NTHREADS)
        (&sm.xp[0][0])[e] = 0.f;
    __syncthreads();

    // ---- load x, y, mask; count unmasked ----
    float cnt = 0.f;
    for (int e = tid; e < TOK_PER_BLK * IDIM; e += NTHREADS) {
        int m = e >> 7, d = e & 127;
        sm.xp[m][127 + d] = x[(tok0 + m) * IDIM + d];
        float yv = y[(tok0 + m) * IDIM + d];
        sm.yres[m][d] = yv;
        unsigned char msk = (yv == 10000.0f) ? 1 : 0;
        sm.ymask[m][d] = msk;
        cnt += msk ? 0.f : 1.f;
    }

    float sqacc = 0.f;
    const int o = tid & 127;    // channel within chunk (B) / output channel (C)
    const int g = tid >> 7;     // token group: tokens 4g..4g+3

    for (int it = 0; it < NITER; ++it) {
        __syncthreads();   // yres/xp stable for phase A

        // ================= Phase A: per-warp token pipeline =================
        {
            const int m = wid;
            float* xpm = sm.xp[m];
            const float*  ym  = sm.yres[m];
            const float4* xp4 = reinterpret_cast<const float4*>(xpm);
            const float4* ym4 = reinterpret_cast<const float4*>(ym);

            // ||y_res||
            float ny2 = 0.f;
            #pragma unroll
            for (int j = 0; j < 4; ++j) { float v = ym[lane + 32 * j]; ny2 += v * v; }
            #pragma unroll
            for (int off = 16; off; off >>= 1) ny2 += __shfl_xor_sync(~0u, ny2, off);
            float ny = sqrtf(ny2);

            // banded correlation: lane handles shifts s = 4*lane + 128*b + j, j=0..3
            float num[8], dn[8];
            #pragma unroll
            for (int k = 0; k < 8; ++k) { num[k] = 0.f; dn[k] = 0.f; }
            #pragma unroll
            for (int b = 0; b < 2; ++b) {
                int q0 = lane + 32 * b;            // float4 base index (s0/4)
                float4 xcur = xp4[q0];
                #pragma unroll 8
                for (int d4 = 0; d4 < 32; ++d4) {
                    float4 yv = ym4[d4];
                    float4 xnx = xp4[q0 + d4 + 1];
                    float xq[8] = {xcur.x, xcur.y, xcur.z, xcur.w,
                                   xnx.x,  xnx.y,  xnx.z,  xnx.w};
                    #pragma unroll
                    for (int j = 0; j < 4; ++j) {
                        int kk = 4 * b + j;
                        float n = num[kk], q = dn[kk];
                        n = fmaf(yv.x, xq[j    ], n); q = fmaf(xq[j    ], xq[j    ], q);
                        n = fmaf(yv.y, xq[j + 1], n); q = fmaf(xq[j + 1], xq[j + 1], q);
                        n = fmaf(yv.z, xq[j + 2], n); q = fmaf(xq[j + 2], xq[j + 2], q);
                        n = fmaf(yv.w, xq[j + 3], n); q = fmaf(xq[j + 3], xq[j + 3], q);
                        num[kk] = n; dn[kk] = q;
                    }
                    xcur = xnx;
                }
            }

            // per-lane first-max (ascending s within lane), then warp first-max
            float best = -INFINITY; int bs = 0x7fffffff;
            #pragma unroll
            for (int b = 0; b < 2; ++b)
            #pragma unroll
            for (int j = 0; j < 4; ++j) {
                int s = 4 * lane + 128 * b + j;
                if (s < 255) {
                    int kk = 4 * b + j;
                    float den = ny * sqrtf(dn[kk]);
                    float sim = (den == 0.f) ? 0.f : num[kk] / den;
                    if (sim > best) { best = sim; bs = s; }
                }
            }
            #pragma unroll
            for (int off = 16; off; off >>= 1) {
                float ob = __shfl_xor_sync(~0u, best, off);
                int   os = __shfl_xor_sync(~0u, bs,   off);
                if (ob > best || (ob == best && os < bs)) { best = ob; bs = os; }
            }
            const int idx = bs;

            // softmax attention: z = x_aug * y_res
            float xav[4], z[4];
            float zmax = -INFINITY;
            #pragma unroll
            for (int j = 0; j < 4; ++j) {
                int d = lane + 32 * j;
                xav[j] = xpm[idx + d];
                z[j]   = xav[j] * ym[d];
                zmax   = fmaxf(zmax, z[j]);
            }
            #pragma unroll
            for (int off = 16; off; off >>= 1) zmax = fmaxf(zmax, __shfl_xor_sync(~0u, zmax, off));
            float es = 0.f, e[4];
            #pragma unroll
            for (int j = 0; j < 4; ++j) { e[j] = expf(z[j] - zmax); es += e[j]; }
            #pragma unroll
            for (int off = 16; off; off >>= 1) es += __shfl_xor_sync(~0u, es, off);
            #pragma unroll
            for (int j = 0; j < 4; ++j) {
                int d = lane + 32 * j;
                sm.xa[m][d] = xav[j] * (e[j] / es);   // x_attn, token-major
            }
            __syncwarp();
            // reverse shift: x_res[d] -= x_attn[d + 127 - idx]
            #pragma unroll
            for (int j = 0; j < 4; ++j) {
                int d = lane + 32 * j;
                int src = d + 127 - idx;
                float xe = (src >= 0 && src < 128) ? sm.xa[m][src] : 0.f;
                xpm[127 + d] -= xe;
            }
        }
        __syncthreads();   // xa ready; xp updates done

        // ================= Phase B: h = x_attn @ W1_slice^T + b1 =================
        const float4* xa4 = reinterpret_cast<const float4*>(&sm.xa[0][0]);
        for (int chunk = 0; chunk < 2; ++chunk) {
            // stage 128 rows of W1 (row-major, padded stride 33 float4)
            const float4* wg = reinterpret_cast<const float4*>(
                w1 + (size_t)(it * 256 + chunk * 128) * IDIM);
            #pragma unroll
            for (int r = 0; r < 16; ++r) {
                int j   = tid + r * 256;       // 0..4095
                int row = j >> 5;
                int c4  = j & 31;
                sm.wst[row * WST_STRIDE + c4] = wg[j];
            }
            __syncthreads();

            float bv = b1[it * 256 + chunk * 128 + o];
            float a0 = bv, a1 = bv, a2 = bv, a3 = bv;
            const float4* wrow = &sm.wst[o * WST_STRIDE];
            #pragma unroll 8
            for (int d4 = 0; d4 < 32; ++d4) {
                float4 w4 = wrow[d4];
                float4 x0 = xa4[(4 * g + 0) * 32 + d4];
                float4 x1 = xa4[(4 * g + 1) * 32 + d4];
                float4 x2 = xa4[(4 * g + 2) * 32 + d4];
                float4 x3 = xa4[(4 * g + 3) * 32 + d4];
                a0 = fmaf(w4.x, x0.x, a0); a0 = fmaf(w4.y, x0.y, a0);
                a0 = fmaf(w4.z, x0.z, a0); a0 = fmaf(w4.w, x0.w, a0);
                a1 = fmaf(w4.x, x1.x, a1); a1 = fmaf(w4.y, x1.y, a1);
                a1 = fmaf(w4.z, x1.z, a1); a1 = fmaf(w4.w, x1.w, a1);
                a2 = fmaf(w4.x, x2.x, a2); a2 = fmaf(w4.y, x2.y, a2);
                a2 = fmaf(w4.z, x2.z, a2); a2 = fmaf(w4.w, x2.w, a2);
                a3 = fmaf(w4.x, x3.x, a3); a3 = fmaf(w4.y, x3.y, a3);
                a3 = fmaf(w4.z, x3.z, a3); a3 = fmaf(w4.w, x3.w, a3);
            }
            sm.h[4 * g + 0][chunk * 128 + o] = a0;
            sm.h[4 * g + 1][chunk * 128 + o] = a1;
            sm.h[4 * g + 2][chunk * 128 + o] = a2;
            sm.h[4 * g + 3][chunk * 128 + o] = a3;
            __syncthreads();
        }

        // ================= Phase C: y_ele = h @ W2_slice^T + b2 =================
        const float4* h4 = reinterpret_cast<const float4*>(&sm.h[0][0]);
        float b2v = b2[o];
        float c0v = b2v, c1v = b2v, c2v = b2v, c3v = b2v;
        for (int chunk = 0; chunk < 2; ++chunk) {
            const float4* wg2 = reinterpret_cast<const float4*>(w2);
            #pragma unroll
            for (int r = 0; r < 16; ++r) {
                int j   = tid + r * 256;
                int row = j >> 5;
                int c4  = j & 31;
                sm.wst[row * WST_STRIDE + c4] =
                    wg2[(size_t)row * (HDIM / 4) + it * 64 + chunk * 32 + c4];
            }
            __syncthreads();

            const float4* wrow = &sm.wst[o * WST_STRIDE];
            #pragma unroll 8
            for (int c4 = 0; c4 < 32; ++c4) {
                float4 w4 = wrow[c4];
                float4 h0 = h4[(4 * g + 0) * (HROW / 4) + chunk * 32 + c4];
                float4 h1 = h4[(4 * g + 1) * (HROW / 4) + chunk * 32 + c4];
                float4 h2 = h4[(4 * g + 2) * (HROW / 4) + chunk * 32 + c4];
                float4 h3 = h4[(4 * g + 3) * (HROW / 4) + chunk * 32 + c4];
                c0v = fmaf(w4.x, h0.x, c0v); c0v = fmaf(w4.y, h0.y, c0v);
                c0v = fmaf(w4.z, h0.z, c0v); c0v = fmaf(w4.w, h0.w, c0v);
                c1v = fmaf(w4.x, h1.x, c1v); c1v = fmaf(w4.y, h1.y, c1v);
                c1v = fmaf(w4.z, h1.z, c1v); c1v = fmaf(w4.w, h1.w, c1v);
                c2v = fmaf(w4.x, h2.x, c2v); c2v = fmaf(w4.y, h2.y, c2v);
                c2v = fmaf(w4.z, h2.z, c2v); c2v = fmaf(w4.w, h2.w, c2v);
                c3v = fmaf(w4.x, h3.x, c3v); c3v = fmaf(w4.y, h3.y, c3v);
                c3v = fmaf(w4.z, h3.z, c3v); c3v = fmaf(w4.w, h3.w, c3v);
            }
            __syncthreads();
        }

        // ---- masked squared error + y_res update ----
        #pragma unroll
        for (int j = 0; j < 4; ++j) {
            int m = 4 * g + j;
            float ye = (j == 0) ? c0v : (j == 1) ? c1v : (j == 2) ? c2v : c3v;
            float yr = sm.yres[m][o];
            if (!sm.ymask[m][o]) { float dd = ye - yr; sqacc += dd * dd; }
            sm.yres[m][o] = yr - ye;
        }
        // next-iteration top __syncthreads orders these writes before phase A
    }

    // ---- block reduction ----
    #pragma unroll
    for (int off = 16; off; off >>= 1) {
        sqacc += __shfl_xor_sync(~0u, sqacc, off);
        cnt   += __shfl_xor_sync(~0u, cnt,   off);
    }
    if (lane == 0) { sm.red[wid] = sqacc; sm.red2[wid] = cnt; }
    __syncthreads();
    if (tid == 0) {
        float s = 0.f, c = 0.f;
        #pragma unroll
        for (int w = 0; w < 8; ++w) { s += sm.red[w]; c += sm.red2[w]; }
        g_psum[blk] = s;
        g_pcnt[blk] = c;
    }
}

__global__ void net_final_kernel(float* __restrict__ out)
{
    __shared__ float ss[NBLK];
    __shared__ float sc[NBLK];
    int t = threadIdx.x;
    ss[t] = g_psum[t];
    sc[t] = g_pcnt[t];
    __syncthreads();
    for (int off = 128; off; off >>= 1) {
        if (t < off) { ss[t] += ss[t + off]; sc[t] += sc[t + off]; }
        __syncthreads();
    }
    if (t == 0) out[0] = ss[0] / (4.0f * sc[0]);
}

extern "C" void kernel_launch(void* const* d_in, const int* in_sizes, int n_in,
                              void* d_out, int out_size)
{
    (void)in_sizes; (void)n_in; (void)out_size;
    const float* x  = (const float*)d_in[0];
    const float* y  = (const float*)d_in[1];
    const float* w1 = (const float*)d_in[2];
    const float* b1 = (const float*)d_in[3];
    const float* w2 = (const float*)d_in[4];
    const float* b2 = (const float*)d_in[5];
    float* out = (float*)d_out;

    cudaFuncSetAttribute(net_main_kernel,
                         cudaFuncAttributeMaxDynamicSharedMemorySize,
                         (int)sizeof(Smem));
    net_main_kernel<<<NBLK, NTHREADS, sizeof(Smem)>>>(x, y, w1, b1, w2, b2);
    net_final_kernel<<<1, NBLK>>>(out);
}